// round 5
// baseline (speedup 1.0000x reference)
#include <cuda_runtime.h>
#include <cuda_fp16.h>
#include <cstdint>

#define H 512
#define W 512
#define NPIX (H * W)

// Packed flow-corner table: entry (i,j) = 16 bytes =
//   half2 f(i,j), half2 f(i,j+1), half2 f(i+1,j), half2 f(i+1,j+1)
// where f = (flow_ch0, flow_ch1). One LDG.128 per bilinear sample.
__device__ uint4 g_F[NPIX];   // 4 MB, L2-resident

__device__ __forceinline__ uint32_t pack_h2(float a, float b) {
    __half2 h = __floats2half2_rn(a, b);
    return *reinterpret_cast<uint32_t*>(&h);
}

__global__ void build_F_kernel(const float* __restrict__ flow) {
    int idx = blockIdx.x * blockDim.x + threadIdx.x;
    if (idx >= NPIX) return;
    int i = idx >> 9;
    int j = idx & (W - 1);
    int i1 = min(i + 1, H - 1);
    int j1 = min(j + 1, W - 1);
    int p00 = (i  << 9) | j;
    int p01 = (i  << 9) | j1;
    int p10 = (i1 << 9) | j;
    int p11 = (i1 << 9) | j1;
    uint4 e;
    e.x = pack_h2(flow[p00], flow[NPIX + p00]);
    e.y = pack_h2(flow[p01], flow[NPIX + p01]);
    e.z = pack_h2(flow[p10], flow[NPIX + p10]);
    e.w = pack_h2(flow[p11], flow[NPIX + p11]);
    g_F[idx] = e;
}

__device__ __forceinline__ float2 unpack_h2(uint32_t u) {
    __half2 h = *reinterpret_cast<__half2*>(&u);
    return __half22float2(h);
}

#define OUT_SCALE (512.0f / 511.0f)

// Per-point state that must live across the gather: 6 floats.
struct PCtx {
    float w00, w10, w01, w11;  // bilinear weights
    float a0, a1;              // analytic grid part: x0+1-yf, y0+1-xf
};

__device__ __forceinline__ int point_setup(float x, float y, bool bilinear, PCtx& c) {
    if (bilinear) {
        float xt = truncf(x);
        float yt = truncf(y);
        float xf = x - xt;
        float yf = y - yt;
        int x0 = (int)xt;
        int y0 = (int)yt;
        float oxf = 1.0f - xf;
        float oyf = 1.0f - yf;
        c.w00 = xf * yf;
        c.w10 = xf * oyf;
        c.w01 = oxf * yf;
        c.w11 = oxf * oyf;
        c.a0 = (float)(x0 + 1) - yf;
        c.a1 = (float)(y0 + 1) - xf;
        return (x0 << 9) | y0;
    } else {
        int xi = min((int)rintf(x), H - 1);
        int yi = min((int)rintf(y), W - 1);
        c.w00 = 1.0f; c.w10 = 0.0f; c.w01 = 0.0f; c.w11 = 0.0f;
        c.a0 = (float)xi;
        c.a1 = (float)yi;
        return (xi << 9) | yi;
    }
}

__device__ __forceinline__ float2 point_finish(const PCtx& c, uint4 e) {
    float2 c00 = unpack_h2(e.x);
    float2 c01 = unpack_h2(e.y);
    float2 c10 = unpack_h2(e.z);
    float2 c11 = unpack_h2(e.w);
    float bf0 = fmaf(c.w00, c00.x, fmaf(c.w10, c10.x, fmaf(c.w01, c01.x, c.w11 * c11.x)));
    float bf1 = fmaf(c.w00, c00.y, fmaf(c.w10, c10.y, fmaf(c.w01, c01.y, c.w11 * c11.y)));
    return make_float2((c.a0 + bf0) * OUT_SCALE, (c.a1 + bf1) * OUT_SCALE);
}

// 4 points per thread, occupancy forced to 7 blocks/SM (regs <= 36).
__global__ void __launch_bounds__(256, 7)
sample_kernel(const float4* __restrict__ pts,
              float4* __restrict__ out,
              const int* __restrict__ intep,
              int n_quad) {
    int idx = blockIdx.x * blockDim.x + threadIdx.x;
    if (idx >= n_quad) return;
    bool bilinear = (*intep) != 0;

    // Streaming loads (evict-first) to keep g_F resident in L2.
    float4 pa = __ldcs(pts + 2 * idx);
    float4 pb = __ldcs(pts + 2 * idx + 1);

    PCtx c0, c1, c2, c3;
    int k0 = point_setup(pa.x, pa.y, bilinear, c0);
    int k1 = point_setup(pa.z, pa.w, bilinear, c1);
    int k2 = point_setup(pb.x, pb.y, bilinear, c2);
    int k3 = point_setup(pb.z, pb.w, bilinear, c3);

    // 4 independent gathers in flight.
    uint4 e0 = __ldg(g_F + k0);
    uint4 e1 = __ldg(g_F + k1);
    uint4 e2 = __ldg(g_F + k2);
    uint4 e3 = __ldg(g_F + k3);

    float2 r0 = point_finish(c0, e0);
    float2 r1 = point_finish(c1, e1);
    float2 r2 = point_finish(c2, e2);
    float2 r3 = point_finish(c3, e3);

    __stcs(out + 2 * idx,     make_float4(r0.x, r0.y, r1.x, r1.y));
    __stcs(out + 2 * idx + 1, make_float4(r2.x, r2.y, r3.x, r3.y));
}

extern "C" void kernel_launch(void* const* d_in, const int* in_sizes, int n_in,
                              void* d_out, int out_size) {
    const float* point = (const float*)d_in[0];   // (1, N, 2)
    const float* flow  = (const float*)d_in[1];   // (1, 2, 512, 512)
    const int*   intep = (const int*)d_in[2];

    build_F_kernel<<<(NPIX + 255) / 256, 256>>>(flow);

    int n_quad = out_size / 8;  // 4 points (8 floats) per thread
    sample_kernel<<<(n_quad + 255) / 256, 256>>>(
        (const float4*)point, (float4*)d_out, intep, n_quad);
}

// round 6
// speedup vs baseline: 1.2684x; 1.2684x over previous
#include <cuda_runtime.h>
#include <cuda_fp16.h>
#include <cstdint>

#define H 512
#define W 512
#define NPIX (H * W)

// Packed flow-corner table: entry (i,j) = 16 bytes =
//   half2 f(i,j), half2 f(i,j+1), half2 f(i+1,j), half2 f(i+1,j+1)
// where f = (flow_ch0, flow_ch1). One LDG.128 per bilinear sample.
__device__ uint4 g_F[NPIX];   // 4 MB, L2-resident

__device__ __forceinline__ uint32_t pack_h2(float a, float b) {
    __half2 h = __floats2half2_rn(a, b);
    return *reinterpret_cast<uint32_t*>(&h);
}

__global__ void build_F_kernel(const float* __restrict__ flow) {
    int idx = blockIdx.x * blockDim.x + threadIdx.x;
    if (idx >= NPIX) return;
    int i = idx >> 9;
    int j = idx & (W - 1);
    int i1 = min(i + 1, H - 1);
    int j1 = min(j + 1, W - 1);
    int p00 = (i  << 9) | j;
    int p01 = (i  << 9) | j1;
    int p10 = (i1 << 9) | j;
    int p11 = (i1 << 9) | j1;
    uint4 e;
    e.x = pack_h2(flow[p00], flow[NPIX + p00]);
    e.y = pack_h2(flow[p01], flow[NPIX + p01]);
    e.z = pack_h2(flow[p10], flow[NPIX + p10]);
    e.w = pack_h2(flow[p11], flow[NPIX + p11]);
    g_F[idx] = e;
}

__device__ __forceinline__ float2 unpack_h2(uint32_t u) {
    __half2 h = *reinterpret_cast<__half2*>(&u);
    return __half22float2(h);
}

#define OUT_SCALE (512.0f / 511.0f)

__device__ __forceinline__ float2 sample_point(float x, float y, bool bilinear) {
    if (bilinear) {
        float xt = truncf(x);
        float yt = truncf(y);
        float xf = x - xt;
        float yf = y - yt;
        int x0 = (int)xt;
        int y0 = (int)yt;
        uint4 e = __ldg(g_F + ((x0 << 9) | y0));
        float2 c00 = unpack_h2(e.x);
        float2 c01 = unpack_h2(e.y);
        float2 c10 = unpack_h2(e.z);
        float2 c11 = unpack_h2(e.w);
        float oxf = 1.0f - xf;
        float oyf = 1.0f - yf;
        float w00 = xf * yf;
        float w10 = xf * oyf;
        float w01 = oxf * yf;
        float w11 = oxf * oyf;
        float bf0 = fmaf(w00, c00.x, fmaf(w10, c10.x, fmaf(w01, c01.x, w11 * c11.x)));
        float bf1 = fmaf(w00, c00.y, fmaf(w10, c10.y, fmaf(w01, c01.y, w11 * c11.y)));
        float out0 = ((float)(x0 + 1) - yf + bf0) * OUT_SCALE;
        float out1 = ((float)(y0 + 1) - xf + bf1) * OUT_SCALE;
        return make_float2(out0, out1);
    } else {
        int xi = min((int)rintf(x), H - 1);
        int yi = min((int)rintf(y), W - 1);
        uint4 e = __ldg(g_F + ((xi << 9) | yi));
        float2 c00 = unpack_h2(e.x);
        return make_float2(((float)xi + c00.x) * OUT_SCALE,
                           ((float)yi + c00.y) * OUT_SCALE);
    }
}

#define GRID_BLOCKS 1184   // 148 SMs * 8 blocks
#define BLOCK 256

// Persistent grid-stride, one-deep pipeline: prefetch next point float4
// while gathering/finishing the current one. 2 points per thread per iter.
__global__ void sample_kernel(const float4* __restrict__ pts,
                              float4* __restrict__ out,
                              const int* __restrict__ intep,
                              int n_vec) {
    int stride = GRID_BLOCKS * BLOCK;
    int i = blockIdx.x * BLOCK + threadIdx.x;
    if (i >= n_vec) return;
    bool bilinear = (*intep) != 0;

    float4 p = pts[i];
    while (true) {
        int inext = i + stride;
        float4 pn;
        bool has_next = inext < n_vec;
        if (has_next) pn = pts[inext];   // prefetch: overlaps with gathers below

        float2 r0 = sample_point(p.x, p.y, bilinear);
        float2 r1 = sample_point(p.z, p.w, bilinear);
        out[i] = make_float4(r0.x, r0.y, r1.x, r1.y);

        if (!has_next) break;
        i = inext;
        p = pn;
    }
}

extern "C" void kernel_launch(void* const* d_in, const int* in_sizes, int n_in,
                              void* d_out, int out_size) {
    const float* point = (const float*)d_in[0];   // (1, N, 2)
    const float* flow  = (const float*)d_in[1];   // (1, 2, 512, 512)
    const int*   intep = (const int*)d_in[2];

    build_F_kernel<<<(NPIX + 255) / 256, 256>>>(flow);

    int n_vec = out_size / 4;  // 2 points per float4
    sample_kernel<<<GRID_BLOCKS, BLOCK>>>(
        (const float4*)point, (float4*)d_out, intep, n_vec);
}